// round 3
// baseline (speedup 1.0000x reference)
#include <cuda_runtime.h>
#include <cstdint>

#define Bsz   64
#define Lseq  1024
#define Hdim  512
#define HALF  256
#define Vvoc  32000
#define BL    (Bsz * Lseq)          // 65536
#define LN_EPS   1e-5f
#define DELTA_EPS 1e-6f

// ---------------- scratch (device globals; no allocations allowed) ----------
__device__ float g_e [ (size_t)BL * Hdim ];        // 33.5M floats
__device__ float g_x1[ (size_t)BL * 2 * Hdim ];    // 67.1M floats (reused for ks/ke)
__device__ float g_h [ (size_t)BL * Hdim ];        // 33.5M floats
__device__ float g_beta[ 2 * BL ];                 // 131072
__device__ float g_c [ Bsz * 2 * HALF ];           // 32768

// ---------------- embedding gather ------------------------------------------
__global__ __launch_bounds__(256) void gather_kernel(
    const int* __restrict__ seq, const float* __restrict__ embed,
    float* __restrict__ e)
{
    size_t i = (size_t)blockIdx.x * blockDim.x + threadIdx.x;  // over BL*(H/4)
    int row  = (int)(i >> 7);          // /128 float4 per row
    int c4   = ((int)i & 127) << 2;
    int tok  = __ldg(&seq[row]);
    float4 v = *(const float4*)(embed + (size_t)tok * Hdim + c4);
    *(float4*)(e + (size_t)row * Hdim + c4) = v;
}

// ---------------- fp32 SGEMM, 128x128 tile, BK=8, 8x8 per thread ------------
// MODE 0: relu(acc + bias)   MODE 1: acc + bias + Res   MODE 2: acc + bias
template<int MODE>
__global__ __launch_bounds__(256) void sgemm_kernel(
    const float* __restrict__ A, const float* __restrict__ Bw,
    const float* __restrict__ bias, const float* __restrict__ Res,
    float* __restrict__ C, int M, int N, int K)
{
    __shared__ float As[8][128];
    __shared__ float Bs[8][128];

    const int tid = threadIdx.x;
    const int bm  = blockIdx.y, bn = blockIdx.x;
    const int tx  = tid & 15, ty = tid >> 4;

    const int arow = tid >> 1, acol = (tid & 1) << 2;   // A tile 128x8
    const int brow = tid >> 5, bcol = (tid & 31) << 2;  // B tile 8x128

    const float* Aptr = A  + (size_t)(bm * 128 + arow) * K + acol;
    const float* Bptr = Bw + (size_t)brow * N + bn * 128 + bcol;

    float4 a_nv = *(const float4*)Aptr;
    float4 b_nv = *(const float4*)Bptr;

    float acc[8][8];
    #pragma unroll
    for (int i = 0; i < 8; i++)
        #pragma unroll
        for (int j = 0; j < 8; j++) acc[i][j] = 0.f;

    for (int k0 = 0; k0 < K; k0 += 8) {
        As[acol + 0][arow] = a_nv.x;
        As[acol + 1][arow] = a_nv.y;
        As[acol + 2][arow] = a_nv.z;
        As[acol + 3][arow] = a_nv.w;
        *(float4*)&Bs[brow][bcol] = b_nv;
        __syncthreads();

        if (k0 + 8 < K) {
            a_nv = *(const float4*)(Aptr + k0 + 8);
            b_nv = *(const float4*)(Bptr + (size_t)(k0 + 8) * N);
        }

        #pragma unroll
        for (int kk = 0; kk < 8; kk++) {
            float a[8], b[8];
            *(float4*)&a[0] = *(float4*)&As[kk][ty * 8];
            *(float4*)&a[4] = *(float4*)&As[kk][ty * 8 + 4];
            *(float4*)&b[0] = *(float4*)&Bs[kk][tx * 8];
            *(float4*)&b[4] = *(float4*)&Bs[kk][tx * 8 + 4];
            #pragma unroll
            for (int i = 0; i < 8; i++)
                #pragma unroll
                for (int j = 0; j < 8; j++)
                    acc[i][j] += a[i] * b[j];
        }
        __syncthreads();
    }

    #pragma unroll
    for (int i = 0; i < 8; i++) {
        int gm = bm * 128 + ty * 8 + i;
        #pragma unroll
        for (int j = 0; j < 8; j += 4) {
            int gn = bn * 128 + tx * 8 + j;
            float4 v;
            v.x = acc[i][j + 0] + bias[gn + 0];
            v.y = acc[i][j + 1] + bias[gn + 1];
            v.z = acc[i][j + 2] + bias[gn + 2];
            v.w = acc[i][j + 3] + bias[gn + 3];
            if (MODE == 0) {
                v.x = fmaxf(v.x, 0.f); v.y = fmaxf(v.y, 0.f);
                v.z = fmaxf(v.z, 0.f); v.w = fmaxf(v.w, 0.f);
            }
            if (MODE == 1) {
                float4 r = *(const float4*)(Res + (size_t)gm * N + gn);
                v.x += r.x; v.y += r.y; v.z += r.z; v.w += r.w;
            }
            *(float4*)(C + (size_t)gm * N + gn) = v;
        }
    }
}

// ---------------- LayerNorm (in place), warp per row ------------------------
__global__ __launch_bounds__(256) void ln_kernel(
    float* __restrict__ x, const float* __restrict__ g, const float* __restrict__ b)
{
    int row  = blockIdx.x * 8 + (threadIdx.x >> 5);
    int lane = threadIdx.x & 31;
    float* xr = x + (size_t)row * Hdim;

    float v[16];
    #pragma unroll
    for (int i = 0; i < 4; i++)
        *(float4*)&v[i * 4] = *(const float4*)(xr + lane * 16 + i * 4);

    float s = 0.f, ss = 0.f;
    #pragma unroll
    for (int i = 0; i < 16; i++) { s += v[i]; ss += v[i] * v[i]; }
    #pragma unroll
    for (int off = 16; off > 0; off >>= 1) {
        s  += __shfl_xor_sync(0xffffffffu, s,  off);
        ss += __shfl_xor_sync(0xffffffffu, ss, off);
    }
    float mu  = s * (1.f / Hdim);
    float var = ss * (1.f / Hdim) - mu * mu;
    float rs  = rsqrtf(var + LN_EPS);

    #pragma unroll
    for (int i = 0; i < 16; i++) {
        int col = lane * 16 + i;
        v[i] = (v[i] - mu) * rs * __ldg(&g[col]) + __ldg(&b[col]);
    }
    #pragma unroll
    for (int i = 0; i < 4; i++)
        *(float4*)(xr + lane * 16 + i * 4) = *(float4*)&v[i * 4];
}

// ---------------- beta = 1/(||k||^2 + eps), warp per row --------------------
__global__ __launch_bounds__(256) void beta_kernel(
    const float* __restrict__ ks, const float* __restrict__ ke,
    float* __restrict__ beta)
{
    int row  = blockIdx.x * 8 + (threadIdx.x >> 5);
    int lane = threadIdx.x & 31;
    const float* kr = (row < BL) ? ks + (size_t)row * HALF
                                 : ke + (size_t)(row - BL) * HALF;
    float4 a = *(const float4*)(kr + lane * 8);
    float4 b = *(const float4*)(kr + lane * 8 + 4);
    float ss = a.x*a.x + a.y*a.y + a.z*a.z + a.w*a.w
             + b.x*b.x + b.y*b.y + b.z*b.z + b.w*b.w;
    #pragma unroll
    for (int off = 16; off > 0; off >>= 1)
        ss += __shfl_xor_sync(0xffffffffu, ss, off);
    if (lane == 0) beta[row] = 1.0f / (ss + DELTA_EPS);
}

// ---------------- delta-rule scan: warp owns 8 rows of M --------------------
// grid 256: b = bx>>2, mat = (bx>>1)&1, rb = bx&1 ; block 512 threads (16 warps)
__global__ __launch_bounds__(512) void scan_kernel(
    const float* __restrict__ ks, const float* __restrict__ ke,
    const float* __restrict__ beta, float* __restrict__ c)
{
    __shared__ float ksm[2][HALF];
    __shared__ float beta_sm[Lseq];

    const int bx  = blockIdx.x;
    const int b   = bx >> 2;
    const int mat = (bx >> 1) & 1;
    const int rb  = bx & 1;
    const int tid = threadIdx.x, warp = tid >> 5, lane = tid & 31;
    const int row0 = rb * 128 + warp * 8;

    const float* Kp = (mat ? ke : ks) + (size_t)b * Lseq * HALF;
    const float* Bt = beta + (mat ? BL : 0) + b * Lseq;

    float M[8][8];
    #pragma unroll
    for (int r = 0; r < 8; r++)
        #pragma unroll
        for (int i = 0; i < 8; i++) M[r][i] = 0.f;

    if (tid < 64) *(float4*)&ksm[0][tid * 4] = *(const float4*)(Kp + tid * 4);
    for (int i = tid; i < Lseq; i += 512) beta_sm[i] = Bt[i];
    __syncthreads();

    const float invL = 1.0f / (float)Lseq;
    int cur = 0;

    for (int t = 0; t < Lseq - 1; t++) {
        float4 nv;
        if (tid < 64)
            nv = *(const float4*)(Kp + (size_t)(t + 1) * HALF + tid * 4);

        float bt = beta_sm[t];
        float w  = mat ? (float)(t + 1) * invL : 1.0f;

        float kr[8];
        *(float4*)&kr[0] = *(float4*)&ksm[cur][lane * 8];
        *(float4*)&kr[4] = *(float4*)&ksm[cur][lane * 8 + 4];

        float vp[8];
        #pragma unroll
        for (int r = 0; r < 8; r++) {
            float s = 0.f;
            #pragma unroll
            for (int i = 0; i < 8; i++) s += M[r][i] * kr[i];
            vp[r] = s;
        }
        #pragma unroll
        for (int off = 16; off > 0; off >>= 1)
            #pragma unroll
            for (int r = 0; r < 8; r++)
                vp[r] += __shfl_xor_sync(0xffffffffu, vp[r], off);

        #pragma unroll
        for (int r = 0; r < 8; r++) {
            float d = (ksm[cur][row0 + r] - vp[r] * bt) * w;
            #pragma unroll
            for (int i = 0; i < 8; i++) M[r][i] += d * kr[i];
        }

        if (tid < 64) *(float4*)&ksm[cur ^ 1][tid * 4] = nv;
        __syncthreads();
        cur ^= 1;
    }

    // final matvec with k_{L-1}
    float kr[8];
    *(float4*)&kr[0] = *(float4*)&ksm[cur][lane * 8];
    *(float4*)&kr[4] = *(float4*)&ksm[cur][lane * 8 + 4];
    float vp[8];
    #pragma unroll
    for (int r = 0; r < 8; r++) {
        float s = 0.f;
        #pragma unroll
        for (int i = 0; i < 8; i++) s += M[r][i] * kr[i];
        vp[r] = s;
    }
    #pragma unroll
    for (int off = 16; off > 0; off >>= 1)
        #pragma unroll
        for (int r = 0; r < 8; r++)
            vp[r] += __shfl_xor_sync(0xffffffffu, vp[r], off);
    if (lane == 0) {
        #pragma unroll
        for (int r = 0; r < 8; r++)
            c[(size_t)b * (2 * HALF) + mat * HALF + row0 + r] = vp[r];
    }
}

// ---------------- final projection to vocab ---------------------------------
__global__ __launch_bounds__(256) void out_gemm_kernel(
    const float* __restrict__ c, const float* __restrict__ W,
    const float* __restrict__ bias, float* __restrict__ out)
{
    __shared__ float cs[16][512];
    const int tid = threadIdx.x;
    const int v   = blockIdx.x * 256 + tid;
    const int b0  = blockIdx.y * 16;

    for (int i = tid; i < 16 * 128; i += 256) {
        int r = i >> 7, c4 = (i & 127) << 2;
        *(float4*)&cs[r][c4] = *(const float4*)&c[(size_t)(b0 + r) * 512 + c4];
    }
    __syncthreads();

    float acc[16];
    #pragma unroll
    for (int r = 0; r < 16; r++) acc[r] = 0.f;

    for (int k0 = 0; k0 < 512; k0 += 4) {
        float w0 = __ldg(&W[(size_t)(k0 + 0) * Vvoc + v]);
        float w1 = __ldg(&W[(size_t)(k0 + 1) * Vvoc + v]);
        float w2 = __ldg(&W[(size_t)(k0 + 2) * Vvoc + v]);
        float w3 = __ldg(&W[(size_t)(k0 + 3) * Vvoc + v]);
        #pragma unroll
        for (int r = 0; r < 16; r++) {
            float4 cv = *(float4*)&cs[r][k0];
            acc[r] += cv.x * w0 + cv.y * w1 + cv.z * w2 + cv.w * w3;
        }
    }
    float bv = __ldg(&bias[v]);
    #pragma unroll
    for (int r = 0; r < 16; r++)
        out[(size_t)(b0 + r) * Vvoc + v] = acc[r] + bv;
}

// ---------------- launch ----------------------------------------------------
extern "C" void kernel_launch(void* const* d_in, const int* in_sizes, int n_in,
                              void* d_out, int out_size)
{
    const int*   seq   = (const int*)  d_in[0];
    const float* embed = (const float*)d_in[1];
    const float* ff_w1 = (const float*)d_in[2];
    const float* ff_b1 = (const float*)d_in[3];
    const float* ff_w2 = (const float*)d_in[4];
    const float* ff_b2 = (const float*)d_in[5];
    const float* ln_g  = (const float*)d_in[6];
    const float* ln_b  = (const float*)d_in[7];
    const float* sem_w = (const float*)d_in[8];
    const float* sem_b = (const float*)d_in[9];
    const float* epi_w = (const float*)d_in[10];
    const float* epi_b = (const float*)d_in[11];
    const float* out_w = (const float*)d_in[12];
    const float* out_b = (const float*)d_in[13];
    float* out = (float*)d_out;

    float *e, *x1, *h, *beta, *c;
    cudaGetSymbolAddress((void**)&e,    g_e);
    cudaGetSymbolAddress((void**)&x1,   g_x1);
    cudaGetSymbolAddress((void**)&h,    g_h);
    cudaGetSymbolAddress((void**)&beta, g_beta);
    cudaGetSymbolAddress((void**)&c,    g_c);
    float* ks = x1;                       // reuse x1 after FFN GEMM2
    float* ke = x1 + (size_t)BL * HALF;

    gather_kernel<<<BL * (Hdim / 4) / 256, 256>>>(seq, embed, e);

    sgemm_kernel<0><<<dim3(2 * Hdim / 128, BL / 128), 256>>>(
        e, ff_w1, ff_b1, nullptr, x1, BL, 2 * Hdim, Hdim);

    sgemm_kernel<1><<<dim3(Hdim / 128, BL / 128), 256>>>(
        x1, ff_w2, ff_b2, e, h, BL, Hdim, 2 * Hdim);

    ln_kernel<<<BL / 8, 256>>>(h, ln_g, ln_b);

    sgemm_kernel<2><<<dim3(HALF / 128, BL / 128), 256>>>(
        h, sem_w, sem_b, nullptr, ks, BL, HALF, Hdim);

    sgemm_kernel<2><<<dim3(HALF / 128, BL / 128), 256>>>(
        h, epi_w, epi_b, nullptr, ke, BL, HALF, Hdim);

    beta_kernel<<<2 * BL / 8, 256>>>(ks, ke, beta);

    scan_kernel<<<Bsz * 2 * 2, 512>>>(ks, ke, beta, c);

    out_gemm_kernel<<<dim3(Vvoc / 256, Bsz / 16), 256>>>(c, out_w, out_b, out);
}

// round 7
// speedup vs baseline: 1.0776x; 1.0776x over previous
#include <cuda_runtime.h>
#include <cstdint>

#define Bsz   64
#define Lseq  1024
#define Hdim  512
#define HALF  256
#define Vvoc  32000
#define BL    (Bsz * Lseq)          // 65536
#define LN_EPS   1e-5f
#define DELTA_EPS 1e-6f

// ---------------- packed fp32x2 helpers (sm_103a FFMA2) ---------------------
__device__ __forceinline__ unsigned long long pack2(float x, float y) {
    unsigned long long r;
    asm("mov.b64 %0, {%1, %2};" : "=l"(r) : "f"(x), "f"(y));
    return r;
}
__device__ __forceinline__ void unpack2(unsigned long long p, float &x, float &y) {
    asm("mov.b64 {%0, %1}, %2;" : "=f"(x), "=f"(y) : "l"(p));
}
__device__ __forceinline__ void ffma2(unsigned long long &d,
                                      unsigned long long a,
                                      unsigned long long b) {
    asm("fma.rn.f32x2 %0, %1, %2, %0;" : "+l"(d) : "l"(a), "l"(b));
}

// ---------------- scratch (device globals; no allocations allowed) ----------
__device__ float g_e [ (size_t)BL * Hdim ];
__device__ float g_x1[ (size_t)BL * 2 * Hdim ];    // reused for ks/ke
__device__ float g_h [ (size_t)BL * Hdim ];
__device__ float g_beta[ 2 * BL ];
__device__ float g_c [ Bsz * 2 * HALF ];

// ---------------- embedding gather ------------------------------------------
__global__ __launch_bounds__(256) void gather_kernel(
    const int* __restrict__ seq, const float* __restrict__ embed,
    float* __restrict__ e)
{
    size_t i = (size_t)blockIdx.x * blockDim.x + threadIdx.x;  // over BL*(H/4)
    int row  = (int)(i >> 7);
    int c4   = ((int)i & 127) << 2;
    int tok  = __ldg(&seq[row]);
    float4 v = *(const float4*)(embed + (size_t)tok * Hdim + c4);
    *(float4*)(e + (size_t)row * Hdim + c4) = v;
}

// ---------------- fp32 SGEMM with FFMA2, 128x128 tile, BK=8, 8x8/thread -----
// MODE 0: relu(acc + bias)   MODE 1: acc + bias + Res   MODE 2: acc + bias
template<int MODE>
__global__ __launch_bounds__(256) void sgemm_kernel(
    const float* __restrict__ A, const float* __restrict__ Bw,
    const float* __restrict__ bias, const float* __restrict__ Res,
    float* __restrict__ C, int M, int N, int K)
{
    __shared__ __align__(16) float As[8][128];
    __shared__ __align__(16) float Bs[8][128];

    const int tid = threadIdx.x;
    const int bm  = blockIdx.y, bn = blockIdx.x;
    const int tx  = tid & 15, ty = tid >> 4;

    const int arow = tid >> 1, acol = (tid & 1) << 2;   // A tile 128x8
    const int brow = tid >> 5, bcol = (tid & 31) << 2;  // B tile 8x128

    const float* Aptr = A  + (size_t)(bm * 128 + arow) * K + acol;
    const float* Bptr = Bw + (size_t)brow * N + bn * 128 + bcol;

    float4 a_nv = *(const float4*)Aptr;
    float4 b_nv = *(const float4*)Bptr;

    unsigned long long acc[8][4];          // 8 rows x 4 col-pairs
    #pragma unroll
    for (int i = 0; i < 8; i++)
        #pragma unroll
        for (int j = 0; j < 4; j++) acc[i][j] = 0ULL;

    for (int k0 = 0; k0 < K; k0 += 8) {
        As[acol + 0][arow] = a_nv.x;
        As[acol + 1][arow] = a_nv.y;
        As[acol + 2][arow] = a_nv.z;
        As[acol + 3][arow] = a_nv.w;
        *(float4*)&Bs[brow][bcol] = b_nv;
        __syncthreads();

        if (k0 + 8 < K) {
            a_nv = *(const float4*)(Aptr + k0 + 8);
            b_nv = *(const float4*)(Bptr + (size_t)(k0 + 8) * N);
        }

        #pragma unroll
        for (int kk = 0; kk < 8; kk++) {
            float a[8];
            *(float4*)&a[0] = *(float4*)&As[kk][ty * 8];
            *(float4*)&a[4] = *(float4*)&As[kk][ty * 8 + 4];
            ulonglong2 bp0 = *(const ulonglong2*)&Bs[kk][tx * 8];
            ulonglong2 bp1 = *(const ulonglong2*)&Bs[kk][tx * 8 + 4];
            unsigned long long bp[4] = {bp0.x, bp0.y, bp1.x, bp1.y};
            #pragma unroll
            for (int i = 0; i < 8; i++) {
                unsigned long long ad = pack2(a[i], a[i]);
                #pragma unroll
                for (int j = 0; j < 4; j++)
                    ffma2(acc[i][j], ad, bp[j]);
            }
        }
        __syncthreads();
    }

    float accf[8][8];
    #pragma unroll
    for (int i = 0; i < 8; i++)
        #pragma unroll
        for (int j = 0; j < 4; j++)
            unpack2(acc[i][j], accf[i][2 * j], accf[i][2 * j + 1]);

    #pragma unroll
    for (int i = 0; i < 8; i++) {
        int gm = bm * 128 + ty * 8 + i;
        #pragma unroll
        for (int j = 0; j < 8; j += 4) {
            int gn = bn * 128 + tx * 8 + j;
            float4 v;
            v.x = accf[i][j + 0] + bias[gn + 0];
            v.y = accf[i][j + 1] + bias[gn + 1];
            v.z = accf[i][j + 2] + bias[gn + 2];
            v.w = accf[i][j + 3] + bias[gn + 3];
            if (MODE == 0) {
                v.x = fmaxf(v.x, 0.f); v.y = fmaxf(v.y, 0.f);
                v.z = fmaxf(v.z, 0.f); v.w = fmaxf(v.w, 0.f);
            }
            if (MODE == 1) {
                float4 r = *(const float4*)(Res + (size_t)gm * N + gn);
                v.x += r.x; v.y += r.y; v.z += r.z; v.w += r.w;
            }
            *(float4*)(C + (size_t)gm * N + gn) = v;
        }
    }
}

// ---------------- LayerNorm (in place), warp per row, coalesced -------------
__global__ __launch_bounds__(256) void ln_kernel(
    float* __restrict__ x, const float* __restrict__ g, const float* __restrict__ b)
{
    int row  = blockIdx.x * 8 + (threadIdx.x >> 5);
    int lane = threadIdx.x & 31;
    float* xr = x + (size_t)row * Hdim;

    float v[16];
    #pragma unroll
    for (int i = 0; i < 4; i++)
        *(float4*)&v[i * 4] = *(const float4*)(xr + (lane + 32 * i) * 4);

    float s = 0.f, ss = 0.f;
    #pragma unroll
    for (int i = 0; i < 16; i++) { s += v[i]; ss += v[i] * v[i]; }
    #pragma unroll
    for (int off = 16; off > 0; off >>= 1) {
        s  += __shfl_xor_sync(0xffffffffu, s,  off);
        ss += __shfl_xor_sync(0xffffffffu, ss, off);
    }
    float mu  = s * (1.f / Hdim);
    float var = ss * (1.f / Hdim) - mu * mu;
    float rs  = rsqrtf(var + LN_EPS);

    #pragma unroll
    for (int i = 0; i < 4; i++) {
        float4 gg = *(const float4*)(g + (lane + 32 * i) * 4);
        float4 bb = *(const float4*)(b + (lane + 32 * i) * 4);
        float4 o;
        o.x = (v[i*4+0] - mu) * rs * gg.x + bb.x;
        o.y = (v[i*4+1] - mu) * rs * gg.y + bb.y;
        o.z = (v[i*4+2] - mu) * rs * gg.z + bb.z;
        o.w = (v[i*4+3] - mu) * rs * gg.w + bb.w;
        *(float4*)(xr + (lane + 32 * i) * 4) = o;
    }
}

// ---------------- beta = 1/(||k||^2 + eps), warp per row --------------------
__global__ __launch_bounds__(256) void beta_kernel(
    const float* __restrict__ ks, const float* __restrict__ ke,
    float* __restrict__ beta)
{
    int row  = blockIdx.x * 8 + (threadIdx.x >> 5);
    int lane = threadIdx.x & 31;
    const float* kr = (row < BL) ? ks + (size_t)row * HALF
                                 : ke + (size_t)(row - BL) * HALF;
    float4 a = *(const float4*)(kr + lane * 8);
    float4 b = *(const float4*)(kr + lane * 8 + 4);
    float ss = a.x*a.x + a.y*a.y + a.z*a.z + a.w*a.w
             + b.x*b.x + b.y*b.y + b.z*b.z + b.w*b.w;
    #pragma unroll
    for (int off = 16; off > 0; off >>= 1)
        ss += __shfl_xor_sync(0xffffffffu, ss, off);
    if (lane == 0) beta[row] = 1.0f / (ss + DELTA_EPS);
}

// ---------------- delta-rule scan: warp owns 8 rows of M, FFMA2 -------------
// grid 256: b = bx>>2, mat = (bx>>1)&1, rb = bx&1 ; block 512 threads
#define SCH 32   // k chunk (timesteps staged in smem)
__global__ __launch_bounds__(512) void scan_kernel(
    const float* __restrict__ ks, const float* __restrict__ ke,
    const float* __restrict__ beta, float* __restrict__ c)
{
    __shared__ __align__(16) float ksm[SCH][HALF];   // 32 KB
    __shared__ float beta_sm[Lseq];                  // 4 KB

    const int bx  = blockIdx.x;
    const int b   = bx >> 2;
    const int mat = (bx >> 1) & 1;
    const int rb  = bx & 1;
    const int tid = threadIdx.x, warp = tid >> 5, lane = tid & 31;
    const int row0 = rb * 128 + warp * 8;

    const float* Kp = (mat ? ke : ks) + (size_t)b * Lseq * HALF;
    const float* Bt = beta + (mat ? BL : 0) + b * Lseq;

    unsigned long long Md[8][4];   // M[r][2c],M[r][2c+1] packed
    #pragma unroll
    for (int r = 0; r < 8; r++)
        #pragma unroll
        for (int cc = 0; cc < 4; cc++) Md[r][cc] = 0ULL;

    for (int i = tid; i < Lseq; i += 512) beta_sm[i] = Bt[i];

    const float invL = 1.0f / (float)Lseq;

    for (int c0 = 0; c0 < Lseq; c0 += SCH) {
        __syncthreads();
        // stage SCH timesteps: SCH*HALF/4 = 2048 float4, 4 per thread
        #pragma unroll
        for (int i = 0; i < (SCH * HALF / 4) / 512; i++) {
            int idx = tid + 512 * i;
            int r   = idx >> 6;            // 64 float4 per row
            int c4  = idx & 63;
            *(float4*)&ksm[r][c4 * 4] =
                *(const float4*)(Kp + (size_t)(c0 + r) * HALF + c4 * 4);
        }
        __syncthreads();

        int tmax = (c0 + SCH < Lseq) ? SCH : SCH - 1;   // skip update at t=L-1
        for (int tt = 0; tt < tmax; tt++) {
            int t = c0 + tt;
            const float* krow = ksm[tt];
            ulonglong2 ka = *(const ulonglong2*)&krow[lane * 8];
            ulonglong2 kb = *(const ulonglong2*)&krow[lane * 8 + 4];
            unsigned long long krd[4] = {ka.x, ka.y, kb.x, kb.y};

            float vp[8];
            #pragma unroll
            for (int r = 0; r < 8; r++) {
                unsigned long long s = 0ULL;
                #pragma unroll
                for (int cc = 0; cc < 4; cc++) ffma2(s, Md[r][cc], krd[cc]);
                float lo, hi; unpack2(s, lo, hi);
                vp[r] = lo + hi;
            }
            #pragma unroll
            for (int off = 16; off > 0; off >>= 1)
                #pragma unroll
                for (int r = 0; r < 8; r++)
                    vp[r] += __shfl_xor_sync(0xffffffffu, vp[r], off);

            float bt = beta_sm[t];
            float w  = mat ? (float)(t + 1) * invL : 1.0f;
            #pragma unroll
            for (int r = 0; r < 8; r++) {
                float d = (krow[row0 + r] - vp[r] * bt) * w;
                unsigned long long dd = pack2(d, d);
                #pragma unroll
                for (int cc = 0; cc < 4; cc++) ffma2(Md[r][cc], dd, krd[cc]);
            }
        }
    }

    // final matvec with k_{L-1} (last row of last staged chunk)
    {
        const float* krow = ksm[SCH - 1];
        ulonglong2 ka = *(const ulonglong2*)&krow[lane * 8];
        ulonglong2 kb = *(const ulonglong2*)&krow[lane * 8 + 4];
        unsigned long long krd[4] = {ka.x, ka.y, kb.x, kb.y};
        float vp[8];
        #pragma unroll
        for (int r = 0; r < 8; r++) {
            unsigned long long s = 0ULL;
            #pragma unroll
            for (int cc = 0; cc < 4; cc++) ffma2(s, Md[r][cc], krd[cc]);
            float lo, hi; unpack2(s, lo, hi);
            vp[r] = lo + hi;
        }
        #pragma unroll
        for (int off = 16; off > 0; off >>= 1)
            #pragma unroll
            for (int r = 0; r < 8; r++)
                vp[r] += __shfl_xor_sync(0xffffffffu, vp[r], off);
        if (lane == 0) {
            #pragma unroll
            for (int r = 0; r < 8; r++)
                c[(size_t)b * (2 * HALF) + mat * HALF + row0 + r] = vp[r];
        }
    }
}

// ---------------- final projection: block covers ALL 64 batch rows ----------
// grid.x = Vvoc/256 ; W read exactly once.
__global__ __launch_bounds__(256) void out_gemm_kernel(
    const float* __restrict__ c, const float* __restrict__ W,
    const float* __restrict__ bias, float* __restrict__ out)
{
    __shared__ __align__(16) float cs[64][32];   // 8 KB k-chunk stage
    const int tid = threadIdx.x;
    const int v   = blockIdx.x * 256 + tid;

    float acc[64];
    #pragma unroll
    for (int r = 0; r < 64; r++) acc[r] = 0.f;

    for (int kc = 0; kc < 512; kc += 32) {
        __syncthreads();
        #pragma unroll
        for (int i = 0; i < 8; i++) {
            int idx = tid + 256 * i;
            int r = idx >> 5, kk = idx & 31;
            cs[r][kk] = c[(size_t)r * 512 + kc + kk];
        }
        __syncthreads();

        #pragma unroll
        for (int k0 = 0; k0 < 32; k0 += 4) {
            float w0 = __ldg(&W[(size_t)(kc + k0 + 0) * Vvoc + v]);
            float w1 = __ldg(&W[(size_t)(kc + k0 + 1) * Vvoc + v]);
            float w2 = __ldg(&W[(size_t)(kc + k0 + 2) * Vvoc + v]);
            float w3 = __ldg(&W[(size_t)(kc + k0 + 3) * Vvoc + v]);
            #pragma unroll
            for (int r = 0; r < 64; r++) {
                float4 cv = *(float4*)&cs[r][k0];
                acc[r] += cv.x * w0 + cv.y * w1 + cv.z * w2 + cv.w * w3;
            }
        }
    }
    float bv = __ldg(&bias[v]);
    #pragma unroll
    for (int r = 0; r < 64; r++)
        out[(size_t)r * Vvoc + v] = acc[r] + bv;
}

// ---------------- launch ----------------------------------------------------
extern "C" void kernel_launch(void* const* d_in, const int* in_sizes, int n_in,
                              void* d_out, int out_size)
{
    const int*   seq   = (const int*)  d_in[0];
    const float* embed = (const float*)d_in[1];
    const float* ff_w1 = (const float*)d_in[2];
    const float* ff_b1 = (const float*)d_in[3];
    const float* ff_w2 = (const float*)d_in[4];
    const float* ff_b2 = (const float*)d_in[5];
    const float* ln_g  = (const float*)d_in[6];
    const float* ln_b  = (const float*)d_in[7];
    const float* sem_w = (const float*)d_in[8];
    const float* sem_b = (const float*)d_in[9];
    const float* epi_w = (const float*)d_in[10];
    const float* epi_b = (const float*)d_in[11];
    const float* out_w = (const float*)d_in[12];
    const float* out_b = (const float*)d_in[13];
    float* out = (float*)d_out;

    float *e, *x1, *h, *beta, *c;
    cudaGetSymbolAddress((void**)&e,    g_e);
    cudaGetSymbolAddress((void**)&x1,   g_x1);
    cudaGetSymbolAddress((void**)&h,    g_h);
    cudaGetSymbolAddress((void**)&beta, g_beta);
    cudaGetSymbolAddress((void**)&c,    g_c);
    float* ks = x1;                       // reuse x1 after FFN GEMM2
    float* ke = x1 + (size_t)BL * HALF;

    gather_kernel<<<BL * (Hdim / 4) / 256, 256>>>(seq, embed, e);

    sgemm_kernel<0><<<dim3(2 * Hdim / 128, BL / 128), 256>>>(
        e, ff_w1, ff_b1, nullptr, x1, BL, 2 * Hdim, Hdim);

    sgemm_kernel<1><<<dim3(Hdim / 128, BL / 128), 256>>>(
        x1, ff_w2, ff_b2, e, h, BL, Hdim, 2 * Hdim);

    ln_kernel<<<BL / 8, 256>>>(h, ln_g, ln_b);

    sgemm_kernel<2><<<dim3(HALF / 128, BL / 128), 256>>>(
        h, sem_w, sem_b, nullptr, ks, BL, HALF, Hdim);

    sgemm_kernel<2><<<dim3(HALF / 128, BL / 128), 256>>>(
        h, epi_w, epi_b, nullptr, ke, BL, HALF, Hdim);

    beta_kernel<<<2 * BL / 8, 256>>>(ks, ke, beta);

    scan_kernel<<<Bsz * 2 * 2, 512>>>(ks, ke, beta, c);

    out_gemm_kernel<<<Vvoc / 256, 256>>>(c, out_w, out_b, out);
}

// round 9
// speedup vs baseline: 1.7784x; 1.6504x over previous
#include <cuda_runtime.h>
#include <cstdint>

#define Bsz   64
#define Lseq  1024
#define Hdim  512
#define HALF  256
#define Vvoc  32000
#define BL    (Bsz * Lseq)          // 65536
#define LN_EPS   1e-5f
#define DELTA_EPS 1e-6f

// ---------------- packed fp32x2 helpers (sm_103a FFMA2) ---------------------
__device__ __forceinline__ unsigned long long pack2(float x, float y) {
    unsigned long long r;
    asm("mov.b64 %0, {%1, %2};" : "=l"(r) : "f"(x), "f"(y));
    return r;
}
__device__ __forceinline__ void unpack2(unsigned long long p, float &x, float &y) {
    asm("mov.b64 {%0, %1}, %2;" : "=f"(x), "=f"(y) : "l"(p));
}
__device__ __forceinline__ void ffma2(unsigned long long &d,
                                      unsigned long long a,
                                      unsigned long long b) {
    asm("fma.rn.f32x2 %0, %1, %2, %0;" : "+l"(d) : "l"(a), "l"(b));
}

// ---------------- tf32 helpers ----------------------------------------------
__device__ __forceinline__ uint32_t f2tf(float x) {
    uint32_t r;
    asm("cvt.rna.tf32.f32 %0, %1;" : "=r"(r) : "f"(x));
    return r;
}
__device__ __forceinline__ void mma_tf32(float c[4],
                                         const uint32_t a[4],
                                         const uint32_t b[2]) {
    asm volatile(
        "mma.sync.aligned.m16n8k8.row.col.f32.tf32.tf32.f32 "
        "{%0,%1,%2,%3}, {%4,%5,%6,%7}, {%8,%9}, {%0,%1,%2,%3};"
        : "+f"(c[0]), "+f"(c[1]), "+f"(c[2]), "+f"(c[3])
        : "r"(a[0]), "r"(a[1]), "r"(a[2]), "r"(a[3]),
          "r"(b[0]), "r"(b[1]));
}

// ---------------- scratch (device globals; no allocations allowed) ----------
__device__ float g_e [ (size_t)BL * Hdim ];
__device__ float g_x1[ (size_t)BL * 2 * Hdim ];    // reused for ks/ke
__device__ float g_h [ (size_t)BL * Hdim ];
__device__ float g_beta[ 2 * BL ];
__device__ float g_c [ Bsz * 2 * HALF ];

// ---------------- embedding gather ------------------------------------------
__global__ __launch_bounds__(256) void gather_kernel(
    const int* __restrict__ seq, const float* __restrict__ embed,
    float* __restrict__ e)
{
    size_t i = (size_t)blockIdx.x * blockDim.x + threadIdx.x;  // over BL*(H/4)
    int row  = (int)(i >> 7);
    int c4   = ((int)i & 127) << 2;
    int tok  = __ldg(&seq[row]);
    float4 v = *(const float4*)(embed + (size_t)tok * Hdim + c4);
    *(float4*)(e + (size_t)row * Hdim + c4) = v;
}

// ---------------- tf32 tensor-core GEMM, 128x128x16 block tile --------------
// MODE 0: relu(acc + bias)   MODE 1: acc + bias + Res   MODE 2: acc + bias
// 256 threads = 8 warps in 2(M) x 4(N); warp tile 64x32 = 4x4 mma m16n8k8.
template<int MODE>
__global__ __launch_bounds__(256, 2) void tgemm_kernel(
    const float* __restrict__ A, const float* __restrict__ Bw,
    const float* __restrict__ bias, const float* __restrict__ Res,
    float* __restrict__ C, int M, int N, int K)
{
    __shared__ uint32_t As[128][20];   // row-major, stride 20 -> conflict-free frags
    __shared__ uint32_t Bs[16][132];   // k-major,  stride 132 -> <=2-way frags

    const int tid  = threadIdx.x;
    const int warp = tid >> 5, lane = tid & 31;
    const int warpM = warp >> 2, warpN = warp & 3;
    const int gid = lane >> 2, tig = lane & 3;
    const int bm = blockIdx.y, bn = blockIdx.x;

    // staging assignment: A 128x16 (8 floats/thread), B 16x128 (8 floats/thread)
    const int sArow = tid >> 1;             // 0..127
    const int sAcol = (tid & 1) * 8;        // 0 or 8
    const int sBrow = tid >> 4;             // 0..15
    const int sBcol = (tid & 15) * 8;       // 0..120

    const float* Aptr = A  + (size_t)(bm * 128 + sArow) * K + sAcol;
    const float* Bptr = Bw + (size_t)sBrow * N + bn * 128 + sBcol;

    float4 av0 = *(const float4*)(Aptr);
    float4 av1 = *(const float4*)(Aptr + 4);
    float4 bv0 = *(const float4*)(Bptr);
    float4 bv1 = *(const float4*)(Bptr + 4);

    float acc[4][4][4];
    #pragma unroll
    for (int i = 0; i < 4; i++)
        #pragma unroll
        for (int j = 0; j < 4; j++)
            #pragma unroll
            for (int q = 0; q < 4; q++) acc[i][j][q] = 0.f;

    for (int k0 = 0; k0 < K; k0 += 16) {
        uint4 pa0 = make_uint4(f2tf(av0.x), f2tf(av0.y), f2tf(av0.z), f2tf(av0.w));
        uint4 pa1 = make_uint4(f2tf(av1.x), f2tf(av1.y), f2tf(av1.z), f2tf(av1.w));
        uint4 pb0 = make_uint4(f2tf(bv0.x), f2tf(bv0.y), f2tf(bv0.z), f2tf(bv0.w));
        uint4 pb1 = make_uint4(f2tf(bv1.x), f2tf(bv1.y), f2tf(bv1.z), f2tf(bv1.w));
        *(uint4*)&As[sArow][sAcol]     = pa0;
        *(uint4*)&As[sArow][sAcol + 4] = pa1;
        *(uint4*)&Bs[sBrow][sBcol]     = pb0;
        *(uint4*)&Bs[sBrow][sBcol + 4] = pb1;
        __syncthreads();

        if (k0 + 16 < K) {
            av0 = *(const float4*)(Aptr + k0 + 16);
            av1 = *(const float4*)(Aptr + k0 + 20);
            bv0 = *(const float4*)(Bptr + (size_t)(k0 + 16) * N);
            bv1 = *(const float4*)(Bptr + (size_t)(k0 + 16) * N + 4);
        }

        #pragma unroll
        for (int ks = 0; ks < 2; ks++) {
            const int kk = ks * 8;
            uint32_t af[4][4];
            #pragma unroll
            for (int mi = 0; mi < 4; mi++) {
                int rb = warpM * 64 + mi * 16 + gid;
                af[mi][0] = As[rb][kk + tig];
                af[mi][1] = As[rb + 8][kk + tig];
                af[mi][2] = As[rb][kk + tig + 4];
                af[mi][3] = As[rb + 8][kk + tig + 4];
            }
            uint32_t bf[4][2];
            #pragma unroll
            for (int ni = 0; ni < 4; ni++) {
                int nb = warpN * 32 + ni * 8 + gid;
                bf[ni][0] = Bs[kk + tig][nb];
                bf[ni][1] = Bs[kk + tig + 4][nb];
            }
            #pragma unroll
            for (int mi = 0; mi < 4; mi++)
                #pragma unroll
                for (int ni = 0; ni < 4; ni++)
                    mma_tf32(acc[mi][ni], af[mi], bf[ni]);
        }
        __syncthreads();
    }

    // epilogue: each mma tile holds (row gid, gid+8) x (col 2*tig, 2*tig+1)
    #pragma unroll
    for (int mi = 0; mi < 4; mi++) {
        #pragma unroll
        for (int ni = 0; ni < 4; ni++) {
            int gm0 = bm * 128 + warpM * 64 + mi * 16 + gid;
            int gn  = bn * 128 + warpN * 32 + ni * 8 + 2 * tig;
            float b0 = bias[gn], b1 = bias[gn + 1];
            #pragma unroll
            for (int half = 0; half < 2; half++) {
                int gm = gm0 + half * 8;
                float v0 = acc[mi][ni][half * 2 + 0] + b0;
                float v1 = acc[mi][ni][half * 2 + 1] + b1;
                if (MODE == 0) { v0 = fmaxf(v0, 0.f); v1 = fmaxf(v1, 0.f); }
                if (MODE == 1) {
                    float2 r = *(const float2*)(Res + (size_t)gm * N + gn);
                    v0 += r.x; v1 += r.y;
                }
                float2 o; o.x = v0; o.y = v1;
                *(float2*)(C + (size_t)gm * N + gn) = o;
            }
        }
    }
}

// ---------------- LayerNorm (in place), warp per row, coalesced -------------
__global__ __launch_bounds__(256) void ln_kernel(
    float* __restrict__ x, const float* __restrict__ g, const float* __restrict__ b)
{
    int row  = blockIdx.x * 8 + (threadIdx.x >> 5);
    int lane = threadIdx.x & 31;
    float* xr = x + (size_t)row * Hdim;

    float v[16];
    #pragma unroll
    for (int i = 0; i < 4; i++)
        *(float4*)&v[i * 4] = *(const float4*)(xr + (lane + 32 * i) * 4);

    float s = 0.f, ss = 0.f;
    #pragma unroll
    for (int i = 0; i < 16; i++) { s += v[i]; ss += v[i] * v[i]; }
    #pragma unroll
    for (int off = 16; off > 0; off >>= 1) {
        s  += __shfl_xor_sync(0xffffffffu, s,  off);
        ss += __shfl_xor_sync(0xffffffffu, ss, off);
    }
    float mu  = s * (1.f / Hdim);
    float var = ss * (1.f / Hdim) - mu * mu;
    float rs  = rsqrtf(var + LN_EPS);

    #pragma unroll
    for (int i = 0; i < 4; i++) {
        float4 gg = *(const float4*)(g + (lane + 32 * i) * 4);
        float4 bb = *(const float4*)(b + (lane + 32 * i) * 4);
        float4 o;
        o.x = (v[i*4+0] - mu) * rs * gg.x + bb.x;
        o.y = (v[i*4+1] - mu) * rs * gg.y + bb.y;
        o.z = (v[i*4+2] - mu) * rs * gg.z + bb.z;
        o.w = (v[i*4+3] - mu) * rs * gg.w + bb.w;
        *(float4*)(xr + (lane + 32 * i) * 4) = o;
    }
}

// ---------------- beta = 1/(||k||^2 + eps), warp per row --------------------
__global__ __launch_bounds__(256) void beta_kernel(
    const float* __restrict__ ks, const float* __restrict__ ke,
    float* __restrict__ beta)
{
    int row  = blockIdx.x * 8 + (threadIdx.x >> 5);
    int lane = threadIdx.x & 31;
    const float* kr = (row < BL) ? ks + (size_t)row * HALF
                                 : ke + (size_t)(row - BL) * HALF;
    float4 a = *(const float4*)(kr + lane * 8);
    float4 b = *(const float4*)(kr + lane * 8 + 4);
    float ss = a.x*a.x + a.y*a.y + a.z*a.z + a.w*a.w
             + b.x*b.x + b.y*b.y + b.z*b.z + b.w*b.w;
    #pragma unroll
    for (int off = 16; off > 0; off >>= 1)
        ss += __shfl_xor_sync(0xffffffffu, ss, off);
    if (lane == 0) beta[row] = 1.0f / (ss + DELTA_EPS);
}

// ---------------- delta-rule scan: warp owns 8 rows of M, FFMA2 -------------
#define SCH 32   // k chunk (timesteps staged in smem)
__global__ __launch_bounds__(512) void scan_kernel(
    const float* __restrict__ ks, const float* __restrict__ ke,
    const float* __restrict__ beta, float* __restrict__ c)
{
    __shared__ __align__(16) float ksm[SCH][HALF];   // 32 KB
    __shared__ float beta_sm[Lseq];                  // 4 KB

    const int bx  = blockIdx.x;
    const int b   = bx >> 2;
    const int mat = (bx >> 1) & 1;
    const int rb  = bx & 1;
    const int tid = threadIdx.x, warp = tid >> 5, lane = tid & 31;
    const int row0 = rb * 128 + warp * 8;

    const float* Kp = (mat ? ke : ks) + (size_t)b * Lseq * HALF;
    const float* Bt = beta + (mat ? BL : 0) + b * Lseq;

    unsigned long long Md[8][4];
    #pragma unroll
    for (int r = 0; r < 8; r++)
        #pragma unroll
        for (int cc = 0; cc < 4; cc++) Md[r][cc] = 0ULL;

    for (int i = tid; i < Lseq; i += 512) beta_sm[i] = Bt[i];

    const float invL = 1.0f / (float)Lseq;

    for (int c0 = 0; c0 < Lseq; c0 += SCH) {
        __syncthreads();
        #pragma unroll
        for (int i = 0; i < (SCH * HALF / 4) / 512; i++) {
            int idx = tid + 512 * i;
            int r   = idx >> 6;
            int c4  = idx & 63;
            *(float4*)&ksm[r][c4 * 4] =
                *(const float4*)(Kp + (size_t)(c0 + r) * HALF + c4 * 4);
        }
        __syncthreads();

        int tmax = (c0 + SCH < Lseq) ? SCH : SCH - 1;
        for (int tt = 0; tt < tmax; tt++) {
            int t = c0 + tt;
            const float* krow = ksm[tt];
            ulonglong2 ka = *(const ulonglong2*)&krow[lane * 8];
            ulonglong2 kb = *(const ulonglong2*)&krow[lane * 8 + 4];
            unsigned long long krd[4] = {ka.x, ka.y, kb.x, kb.y};

            float vp[8];
            #pragma unroll
            for (int r = 0; r < 8; r++) {
                unsigned long long s = 0ULL;
                #pragma unroll
                for (int cc = 0; cc < 4; cc++) ffma2(s, Md[r][cc], krd[cc]);
                float lo, hi; unpack2(s, lo, hi);
                vp[r] = lo + hi;
            }
            #pragma unroll
            for (int off = 16; off > 0; off >>= 1)
                #pragma unroll
                for (int r = 0; r < 8; r++)
                    vp[r] += __shfl_xor_sync(0xffffffffu, vp[r], off);

            float bt = beta_sm[t];
            float w  = mat ? (float)(t + 1) * invL : 1.0f;
            #pragma unroll
            for (int r = 0; r < 8; r++) {
                float d = (krow[row0 + r] - vp[r] * bt) * w;
                unsigned long long dd = pack2(d, d);
                #pragma unroll
                for (int cc = 0; cc < 4; cc++) ffma2(Md[r][cc], dd, krd[cc]);
            }
        }
    }

    {
        const float* krow = ksm[SCH - 1];
        ulonglong2 ka = *(const ulonglong2*)&krow[lane * 8];
        ulonglong2 kb = *(const ulonglong2*)&krow[lane * 8 + 4];
        unsigned long long krd[4] = {ka.x, ka.y, kb.x, kb.y};
        float vp[8];
        #pragma unroll
        for (int r = 0; r < 8; r++) {
            unsigned long long s = 0ULL;
            #pragma unroll
            for (int cc = 0; cc < 4; cc++) ffma2(s, Md[r][cc], krd[cc]);
            float lo, hi; unpack2(s, lo, hi);
            vp[r] = lo + hi;
        }
        #pragma unroll
        for (int off = 16; off > 0; off >>= 1)
            #pragma unroll
            for (int r = 0; r < 8; r++)
                vp[r] += __shfl_xor_sync(0xffffffffu, vp[r], off);
        if (lane == 0) {
            #pragma unroll
            for (int r = 0; r < 8; r++)
                c[(size_t)b * (2 * HALF) + mat * HALF + row0 + r] = vp[r];
        }
    }
}

// ---------------- final projection: block covers ALL 64 batch rows ----------
__global__ __launch_bounds__(256) void out_gemm_kernel(
    const float* __restrict__ c, const float* __restrict__ W,
    const float* __restrict__ bias, float* __restrict__ out)
{
    __shared__ __align__(16) float cs[64][32];
    const int tid = threadIdx.x;
    const int v   = blockIdx.x * 256 + tid;

    float acc[64];
    #pragma unroll
    for (int r = 0; r < 64; r++) acc[r] = 0.f;

    for (int kc = 0; kc < 512; kc += 32) {
        __syncthreads();
        #pragma unroll
        for (int i = 0; i < 8; i++) {
            int idx = tid + 256 * i;
            int r = idx >> 5, kk = idx & 31;
            cs[r][kk] = c[(size_t)r * 512 + kc + kk];
        }
        __syncthreads();

        #pragma unroll
        for (int k0 = 0; k0 < 32; k0 += 4) {
            float w0 = __ldg(&W[(size_t)(kc + k0 + 0) * Vvoc + v]);
            float w1 = __ldg(&W[(size_t)(kc + k0 + 1) * Vvoc + v]);
            float w2 = __ldg(&W[(size_t)(kc + k0 + 2) * Vvoc + v]);
            float w3 = __ldg(&W[(size_t)(kc + k0 + 3) * Vvoc + v]);
            #pragma unroll
            for (int r = 0; r < 64; r++) {
                float4 cv = *(float4*)&cs[r][k0];
                acc[r] += cv.x * w0 + cv.y * w1 + cv.z * w2 + cv.w * w3;
            }
        }
    }
    float bv = __ldg(&bias[v]);
    #pragma unroll
    for (int r = 0; r < 64; r++)
        out[(size_t)r * Vvoc + v] = acc[r] + bv;
}

// ---------------- launch ----------------------------------------------------
extern "C" void kernel_launch(void* const* d_in, const int* in_sizes, int n_in,
                              void* d_out, int out_size)
{
    const int*   seq   = (const int*)  d_in[0];
    const float* embed = (const float*)d_in[1];
    const float* ff_w1 = (const float*)d_in[2];
    const float* ff_b1 = (const float*)d_in[3];
    const float* ff_w2 = (const float*)d_in[4];
    const float* ff_b2 = (const float*)d_in[5];
    const float* ln_g  = (const float*)d_in[6];
    const float* ln_b  = (const float*)d_in[7];
    const float* sem_w = (const float*)d_in[8];
    const float* sem_b = (const float*)d_in[9];
    const float* epi_w = (const float*)d_in[10];
    const float* epi_b = (const float*)d_in[11];
    const float* out_w = (const float*)d_in[12];
    const float* out_b = (const float*)d_in[13];
    float* out = (float*)d_out;

    float *e, *x1, *h, *beta, *c;
    cudaGetSymbolAddress((void**)&e,    g_e);
    cudaGetSymbolAddress((void**)&x1,   g_x1);
    cudaGetSymbolAddress((void**)&h,    g_h);
    cudaGetSymbolAddress((void**)&beta, g_beta);
    cudaGetSymbolAddress((void**)&c,    g_c);
    float* ks = x1;                       // reuse x1 after FFN GEMM2
    float* ke = x1 + (size_t)BL * HALF;

    gather_kernel<<<BL * (Hdim / 4) / 256, 256>>>(seq, embed, e);

    tgemm_kernel<0><<<dim3(2 * Hdim / 128, BL / 128), 256>>>(
        e, ff_w1, ff_b1, nullptr, x1, BL, 2 * Hdim, Hdim);

    tgemm_kernel<1><<<dim3(Hdim / 128, BL / 128), 256>>>(
        x1, ff_w2, ff_b2, e, h, BL, Hdim, 2 * Hdim);

    ln_kernel<<<BL / 8, 256>>>(h, ln_g, ln_b);

    tgemm_kernel<2><<<dim3(HALF / 128, BL / 128), 256>>>(
        h, sem_w, sem_b, nullptr, ks, BL, HALF, Hdim);

    tgemm_kernel<2><<<dim3(HALF / 128, BL / 128), 256>>>(
        h, epi_w, epi_b, nullptr, ke, BL, HALF, Hdim);

    beta_kernel<<<2 * BL / 8, 256>>>(ks, ke, beta);

    scan_kernel<<<Bsz * 2 * 2, 512>>>(ks, ke, beta, c);

    out_gemm_kernel<<<Vvoc / 256, 256>>>(c, out_w, out_b, out);
}

// round 16
// speedup vs baseline: 1.8620x; 1.0470x over previous
#include <cuda_runtime.h>
#include <cstdint>

#define Bsz   64
#define Lseq  1024
#define Hdim  512
#define HALF  256
#define Vvoc  32000
#define BL    (Bsz * Lseq)          // 65536
#define LN_EPS   1e-5f
#define DELTA_EPS 1e-6f

// ---------------- packed fp32x2 helpers (sm_103a FFMA2) ---------------------
__device__ __forceinline__ unsigned long long pack2(float x, float y) {
    unsigned long long r;
    asm("mov.b64 %0, {%1, %2};" : "=l"(r) : "f"(x), "f"(y));
    return r;
}
__device__ __forceinline__ void unpack2(unsigned long long p, float &x, float &y) {
    asm("mov.b64 {%0, %1}, %2;" : "=f"(x), "=f"(y) : "l"(p));
}
__device__ __forceinline__ void ffma2(unsigned long long &d,
                                      unsigned long long a,
                                      unsigned long long b) {
    asm("fma.rn.f32x2 %0, %1, %2, %0;" : "+l"(d) : "l"(a), "l"(b));
}

// ---------------- tf32 helpers ----------------------------------------------
__device__ __forceinline__ uint32_t f2tf(float x) {
    uint32_t r;
    asm("cvt.rna.tf32.f32 %0, %1;" : "=r"(r) : "f"(x));
    return r;
}
__device__ __forceinline__ void mma_tf32(float c[4],
                                         const uint32_t a[4],
                                         const uint32_t b[2]) {
    asm volatile(
        "mma.sync.aligned.m16n8k8.row.col.f32.tf32.tf32.f32 "
        "{%0,%1,%2,%3}, {%4,%5,%6,%7}, {%8,%9}, {%0,%1,%2,%3};"
        : "+f"(c[0]), "+f"(c[1]), "+f"(c[2]), "+f"(c[3])
        : "r"(a[0]), "r"(a[1]), "r"(a[2]), "r"(a[3]),
          "r"(b[0]), "r"(b[1]));
}
__device__ __forceinline__ uint32_t smem_u32(const void* p) {
    uint32_t a;
    asm("{ .reg .u64 t; cvta.to.shared.u64 t, %1; cvt.u32.u64 %0, t; }"
        : "=r"(a) : "l"(p));
    return a;
}
#define CPA16(dst, src) \
    asm volatile("cp.async.ca.shared.global [%0], [%1], 16;" \
                 :: "r"(dst), "l"(src))
#define CP_COMMIT() asm volatile("cp.async.commit_group;" ::: "memory")
#define CP_WAIT1()  asm volatile("cp.async.wait_group 1;" ::: "memory")

// ---------------- scratch (device globals; no allocations allowed) ----------
__device__ float    g_e   [ (size_t)BL * Hdim ];      // fp32 embeddings (residual)
__device__ uint32_t g_etf [ (size_t)BL * Hdim ];      // tf32 embeddings (GEMM1 A)
__device__ uint32_t g_x1tf[ (size_t)BL * 2 * Hdim ];  // tf32 relu out (GEMM2 A)
__device__ float    g_h   [ (size_t)BL * Hdim ];      // fp32 FFN out (ln in)
__device__ uint32_t g_htf [ (size_t)BL * Hdim ];      // tf32 ln out (GEMM3 A)
__device__ float    g_kse [ (size_t)BL * 2 * HALF ];  // fused ks|ke, stride 512
__device__ float    g_beta[ 2 * BL ];
__device__ float    g_c   [ Bsz * 2 * HALF ];
__device__ uint32_t g_wt1 [ 1024 * 512 ];             // ff_w1^T tf32
__device__ uint32_t g_wt2 [ 512 * 1024 ];             // ff_w2^T tf32
__device__ uint32_t g_wtse[ 512 * 512 ];              // [sem_w^T ; epi_w^T] tf32
__device__ float    g_bse [ 512 ];                    // [sem_b ; epi_b]

// ---------------- weight transpose + tf32 convert ---------------------------
// W[K][N] row-major -> WT[N][K] tf32 bits
__global__ __launch_bounds__(256) void transpose_tf32_kernel(
    const float* __restrict__ W, uint32_t* __restrict__ WT, int K, int N)
{
    __shared__ float tile[32][33];
    int nb = blockIdx.x * 32, kb = blockIdx.y * 32;
    int x = threadIdx.x & 31, y = (threadIdx.x >> 5) * 4;
    #pragma unroll
    for (int j = 0; j < 4; j++)
        tile[y + j][x] = W[(size_t)(kb + y + j) * N + nb + x];
    __syncthreads();
    #pragma unroll
    for (int j = 0; j < 4; j++)
        WT[(size_t)(nb + y + j) * K + kb + x] = f2tf(tile[x][y + j]);
}

__global__ void pack_bias_kernel(const float* __restrict__ sb,
                                 const float* __restrict__ eb,
                                 float* __restrict__ bse)
{
    int t = blockIdx.x * 256 + threadIdx.x;
    bse[t] = (t < 256) ? sb[t] : eb[t - 256];
}

// ---------------- embedding gather (fp32 + tf32 copies) ---------------------
__global__ __launch_bounds__(256) void gather_kernel(
    const int* __restrict__ seq, const float* __restrict__ embed,
    float* __restrict__ e, uint32_t* __restrict__ etf)
{
    size_t i = (size_t)blockIdx.x * blockDim.x + threadIdx.x;
    int row  = (int)(i >> 7);
    int c4   = ((int)i & 127) << 2;
    int tok  = __ldg(&seq[row]);
    float4 v = *(const float4*)(embed + (size_t)tok * Hdim + c4);
    *(float4*)(e + (size_t)row * Hdim + c4) = v;
    uint4 t = make_uint4(f2tf(v.x), f2tf(v.y), f2tf(v.z), f2tf(v.w));
    *(uint4*)(etf + (size_t)row * Hdim + c4) = t;
}

// ---------------- tf32 mma.sync GEMM with cp.async double buffering ---------
// C[M,N] = A[M,K] * WT[N,K]^T ; A, WT pre-converted tf32 bits in gmem.
// 256 threads = 8 warps (2M x 4N); warp tile 64x32 = 4x4 m16n8k8; BK=16.
// MODE 0: relu(acc+bias) -> tf32 u32 out
// MODE 1: acc+bias+Res   -> fp32 out
// MODE 2: acc+bias       -> fp32 out
template<int MODE>
__global__ __launch_bounds__(256) void tc_gemm_kernel(
    const uint32_t* __restrict__ A, const uint32_t* __restrict__ BT,
    const float* __restrict__ bias, const float* __restrict__ Res,
    void* __restrict__ Cout, int M, int N, int K)
{
    __shared__ __align__(16) uint32_t sA[2][128][20];   // [stage][row][k+pad]
    __shared__ __align__(16) uint32_t sB[2][128][20];   // [stage][n  ][k+pad]

    const int tid  = threadIdx.x;
    const int warp = tid >> 5, lane = tid & 31;
    const int warpM = warp >> 2, warpN = warp & 3;
    const int gid = lane >> 2, tig = lane & 3;
    const int bm = blockIdx.y, bn = blockIdx.x;

    // staging: each thread owns one row-half: 8 u32 = 2 x 16B chunks
    const int srow = tid >> 1;
    const int scol = (tid & 1) * 8;

    const uint32_t* Ag = A  + (size_t)(bm * 128 + srow) * K + scol;
    const uint32_t* Bg = BT + (size_t)(bn * 128 + srow) * K + scol;

    uint32_t adst[2], bdst[2];
    adst[0] = smem_u32(&sA[0][srow][scol]);
    adst[1] = smem_u32(&sA[1][srow][scol]);
    bdst[0] = smem_u32(&sB[0][srow][scol]);
    bdst[1] = smem_u32(&sB[1][srow][scol]);

    // prologue: stages 0 and 1
    CPA16(adst[0],      Ag);
    CPA16(adst[0] + 16, Ag + 4);
    CPA16(bdst[0],      Bg);
    CPA16(bdst[0] + 16, Bg + 4);
    CP_COMMIT();
    CPA16(adst[1],      Ag + 16);
    CPA16(adst[1] + 16, Ag + 20);
    CPA16(bdst[1],      Bg + 16);
    CPA16(bdst[1] + 16, Bg + 20);
    CP_COMMIT();

    float acc[4][4][4];
    #pragma unroll
    for (int i = 0; i < 4; i++)
        #pragma unroll
        for (int j = 0; j < 4; j++)
            #pragma unroll
            for (int q = 0; q < 4; q++) acc[i][j][q] = 0.f;

    const int iters = K >> 4;
    for (int it = 0; it < iters; it++) {
        CP_WAIT1();                 // oldest pending stage (it) complete
        __syncthreads();
        const int st = it & 1;

        #pragma unroll
        for (int ks = 0; ks < 2; ks++) {
            const int kk = ks * 8;
            uint32_t af[4][4];
            #pragma unroll
            for (int mi = 0; mi < 4; mi++) {
                int rb = warpM * 64 + mi * 16 + gid;
                af[mi][0] = sA[st][rb][kk + tig];
                af[mi][1] = sA[st][rb + 8][kk + tig];
                af[mi][2] = sA[st][rb][kk + tig + 4];
                af[mi][3] = sA[st][rb + 8][kk + tig + 4];
            }
            uint32_t bf[4][2];
            #pragma unroll
            for (int ni = 0; ni < 4; ni++) {
                int nb = warpN * 32 + ni * 8 + gid;
                bf[ni][0] = sB[st][nb][kk + tig];
                bf[ni][1] = sB[st][nb][kk + tig + 4];
            }
            #pragma unroll
            for (int mi = 0; mi < 4; mi++)
                #pragma unroll
                for (int ni = 0; ni < 4; ni++)
                    mma_tf32(acc[mi][ni], af[mi], bf[ni]);
        }
        __syncthreads();            // all warps done reading stage st

        if (it + 2 < iters) {       // refill the buffer just consumed
            int k0 = (it + 2) << 4;
            CPA16(adst[st],      Ag + k0);
            CPA16(adst[st] + 16, Ag + k0 + 4);
            CPA16(bdst[st],      Bg + k0);
            CPA16(bdst[st] + 16, Bg + k0 + 4);
        }
        CP_COMMIT();                // empty groups keep wait accounting uniform
    }

    // epilogue: mma tile -> rows (gid, gid+8), cols (2*tig, 2*tig+1)
    #pragma unroll
    for (int mi = 0; mi < 4; mi++) {
        #pragma unroll
        for (int ni = 0; ni < 4; ni++) {
            int gm0 = bm * 128 + warpM * 64 + mi * 16 + gid;
            int gn  = bn * 128 + warpN * 32 + ni * 8 + 2 * tig;
            float b0 = bias[gn], b1 = bias[gn + 1];
            #pragma unroll
            for (int half = 0; half < 2; half++) {
                int gm = gm0 + half * 8;
                float v0 = acc[mi][ni][half * 2 + 0] + b0;
                float v1 = acc[mi][ni][half * 2 + 1] + b1;
                if (MODE == 0) {
                    v0 = fmaxf(v0, 0.f); v1 = fmaxf(v1, 0.f);
                    uint2 o; o.x = f2tf(v0); o.y = f2tf(v1);
                    *(uint2*)((uint32_t*)Cout + (size_t)gm * N + gn) = o;
                } else {
                    if (MODE == 1) {
                        float2 r = *(const float2*)(Res + (size_t)gm * N + gn);
                        v0 += r.x; v1 += r.y;
                    }
                    float2 o; o.x = v0; o.y = v1;
                    *(float2*)((float*)Cout + (size_t)gm * N + gn) = o;
                }
            }
        }
    }
}

// ---------------- LayerNorm: read fp32 h, write tf32 bits -------------------
__global__ __launch_bounds__(256) void ln_kernel(
    const float* __restrict__ x, uint32_t* __restrict__ xo,
    const float* __restrict__ g, const float* __restrict__ b)
{
    int row  = blockIdx.x * 8 + (threadIdx.x >> 5);
    int lane = threadIdx.x & 31;
    const float* xr = x + (size_t)row * Hdim;
    uint32_t* xw = xo + (size_t)row * Hdim;

    float v[16];
    #pragma unroll
    for (int i = 0; i < 4; i++)
        *(float4*)&v[i * 4] = *(const float4*)(xr + (lane + 32 * i) * 4);

    float s = 0.f, ss = 0.f;
    #pragma unroll
    for (int i = 0; i < 16; i++) { s += v[i]; ss += v[i] * v[i]; }
    #pragma unroll
    for (int off = 16; off > 0; off >>= 1) {
        s  += __shfl_xor_sync(0xffffffffu, s,  off);
        ss += __shfl_xor_sync(0xffffffffu, ss, off);
    }
    float mu  = s * (1.f / Hdim);
    float var = ss * (1.f / Hdim) - mu * mu;
    float rs  = rsqrtf(var + LN_EPS);

    #pragma unroll
    for (int i = 0; i < 4; i++) {
        float4 gg = *(const float4*)(g + (lane + 32 * i) * 4);
        float4 bb = *(const float4*)(b + (lane + 32 * i) * 4);
        uint4 o;
        o.x = f2tf((v[i*4+0] - mu) * rs * gg.x + bb.x);
        o.y = f2tf((v[i*4+1] - mu) * rs * gg.y + bb.y);
        o.z = f2tf((v[i*4+2] - mu) * rs * gg.z + bb.z);
        o.w = f2tf((v[i*4+3] - mu) * rs * gg.w + bb.w);
        *(uint4*)(xw + (lane + 32 * i) * 4) = o;
    }
}

// ---------------- beta = 1/(||k||^2 + eps); kse layout stride 512 -----------
__global__ __launch_bounds__(256) void beta_kernel(
    const float* __restrict__ kse, float* __restrict__ beta)
{
    int row  = blockIdx.x * 8 + (threadIdx.x >> 5);
    int lane = threadIdx.x & 31;
    const float* kr = (row < BL) ? kse + (size_t)row * 512
                                 : kse + (size_t)(row - BL) * 512 + 256;
    float4 a = *(const float4*)(kr + lane * 8);
    float4 b = *(const float4*)(kr + lane * 8 + 4);
    float ss = a.x*a.x + a.y*a.y + a.z*a.z + a.w*a.w
             + b.x*b.x + b.y*b.y + b.z*b.z + b.w*b.w;
    #pragma unroll
    for (int off = 16; off > 0; off >>= 1)
        ss += __shfl_xor_sync(0xffffffffu, ss, off);
    if (lane == 0) beta[row] = 1.0f / (ss + DELTA_EPS);
}

// ---------------- delta-rule scan: warp owns 8 rows of M, FFMA2 -------------
#define SCH 32
__global__ __launch_bounds__(512) void scan_kernel(
    const float* __restrict__ kse,
    const float* __restrict__ beta, float* __restrict__ c)
{
    __shared__ __align__(16) float ksm[SCH][HALF];
    __shared__ float beta_sm[Lseq];

    const int bx  = blockIdx.x;
    const int b   = bx >> 2;
    const int mat = (bx >> 1) & 1;
    const int rb  = bx & 1;
    const int tid = threadIdx.x, warp = tid >> 5, lane = tid & 31;
    const int row0 = rb * 128 + warp * 8;

    const float* Kp = kse + (size_t)b * Lseq * 512 + mat * HALF;
    const float* Bt = beta + (mat ? BL : 0) + b * Lseq;

    unsigned long long Md[8][4];
    #pragma unroll
    for (int r = 0; r < 8; r++)
        #pragma unroll
        for (int cc = 0; cc < 4; cc++) Md[r][cc] = 0ULL;

    for (int i = tid; i < Lseq; i += 512) beta_sm[i] = Bt[i];

    const float invL = 1.0f / (float)Lseq;

    for (int c0 = 0; c0 < Lseq; c0 += SCH) {
        __syncthreads();
        #pragma unroll
        for (int i = 0; i < (SCH * HALF / 4) / 512; i++) {
            int idx = tid + 512 * i;
            int r   = idx >> 6;
            int c4  = idx & 63;
            *(float4*)&ksm[r][c4 * 4] =
                *(const float4*)(Kp + (size_t)(c0 + r) * 512 + c4 * 4);
        }
        __syncthreads();

        int tmax = (c0 + SCH < Lseq) ? SCH : SCH - 1;
        for (int tt = 0; tt < tmax; tt++) {
            int t = c0 + tt;
            const float* krow = ksm[tt];
            ulonglong2 ka = *(const ulonglong2*)&krow[lane * 8];
            ulonglong2 kb = *(const ulonglong2*)&krow[lane * 8 + 4];
            unsigned long long krd[4] = {ka.x, ka.y, kb.x, kb.y};

            float vp[8];
            #pragma unroll
            for (int r = 0; r < 8; r++) {
                unsigned long long s = 0ULL;
                #pragma unroll
                for (int cc = 0; cc < 4; cc++) ffma2(s, Md[r][cc], krd[cc]);
                float lo, hi; unpack2(s, lo, hi);
                vp[r] = lo + hi;
            }
            #pragma unroll
            for (int off = 16; off > 0; off >>= 1)
                #pragma unroll
                for (int r = 0; r < 8; r++)
                    vp[r] += __shfl_xor_sync(0xffffffffu, vp[r], off);

            float bt = beta_sm[t];
            float w  = mat ? (float)(t + 1) * invL : 1.0f;
            #pragma unroll
            for (int r = 0; r < 8; r++) {
                float d = (krow[row0 + r] - vp[r] * bt) * w;
                unsigned long long dd = pack2(d, d);
                #pragma unroll
                for (int cc = 0; cc < 4; cc++) ffma2(Md[r][cc], dd, krd[cc]);
            }
        }
    }

    {
        const float* krow = ksm[SCH - 1];
        ulonglong2 ka = *(const ulonglong2*)&krow[lane * 8];
        ulonglong2 kb = *(const ulonglong2*)&krow[lane * 8 + 4];
        unsigned long long krd[4] = {ka.x, ka.y, kb.x, kb.y};
        float vp[8];
        #pragma unroll
        for (int r = 0; r < 8; r++) {
            unsigned long long s = 0ULL;
            #pragma unroll
            for (int cc = 0; cc < 4; cc++) ffma2(s, Md[r][cc], krd[cc]);
            float lo, hi; unpack2(s, lo, hi);
            vp[r] = lo + hi;
        }
        #pragma unroll
        for (int off = 16; off > 0; off >>= 1)
            #pragma unroll
            for (int r = 0; r < 8; r++)
                vp[r] += __shfl_xor_sync(0xffffffffu, vp[r], off);
        if (lane == 0) {
            #pragma unroll
            for (int r = 0; r < 8; r++)
                c[(size_t)b * (2 * HALF) + mat * HALF + row0 + r] = vp[r];
        }
    }
}

// ---------------- final projection: block covers ALL 64 batch rows ----------
__global__ __launch_bounds__(256) void out_gemm_kernel(
    const float* __restrict__ c, const float* __restrict__ W,
    const float* __restrict__ bias, float* __restrict__ out)
{
    __shared__ __align__(16) float cs[64][32];
    const int tid = threadIdx.x;
    const int v   = blockIdx.x * 256 + tid;

    float acc[64];
    #pragma unroll
    for (int r = 0; r < 64; r++) acc[r] = 0.f;

    for (int kc = 0; kc < 512; kc += 32) {
        __syncthreads();
        #pragma unroll
        for (int i = 0; i < 8; i++) {
            int idx = tid + 256 * i;
            int r = idx >> 5, kk = idx & 31;
            cs[r][kk] = c[(size_t)r * 512 + kc + kk];
        }
        __syncthreads();

        #pragma unroll
        for (int k0 = 0; k0 < 32; k0 += 4) {
            float w0 = __ldg(&W[(size_t)(kc + k0 + 0) * Vvoc + v]);
            float w1 = __ldg(&W[(size_t)(kc + k0 + 1) * Vvoc + v]);
            float w2 = __ldg(&W[(size_t)(kc + k0 + 2) * Vvoc + v]);
            float w3 = __ldg(&W[(size_t)(kc + k0 + 3) * Vvoc + v]);
            #pragma unroll
            for (int r = 0; r < 64; r++) {
                float4 cv = *(float4*)&cs[r][k0];
                acc[r] += cv.x * w0 + cv.y * w1 + cv.z * w2 + cv.w * w3;
            }
        }
    }
    float bv = __ldg(&bias[v]);
    #pragma unroll
    for (int r = 0; r < 64; r++)
        out[(size_t)r * Vvoc + v] = acc[r] + bv;
}

// ---------------- launch ----------------------------------------------------
extern "C" void kernel_launch(void* const* d_in, const int* in_sizes, int n_in,
                              void* d_out, int out_size)
{
    const int*   seq   = (const int*)  d_in[0];
    const float* embed = (const float*)d_in[1];
    const float* ff_w1 = (const float*)d_in[2];
    const float* ff_b1 = (const float*)d_in[3];
    const float* ff_w2 = (const float*)d_in[4];
    const float* ff_b2 = (const float*)d_in[5];
    const float* ln_g  = (const float*)d_in[6];
    const float* ln_b  = (const float*)d_in[7];
    const float* sem_w = (const float*)d_in[8];
    const float* sem_b = (const float*)d_in[9];
    const float* epi_w = (const float*)d_in[10];
    const float* epi_b = (const float*)d_in[11];
    const float* out_w = (const float*)d_in[12];
    const float* out_b = (const float*)d_in[13];
    float* out = (float*)d_out;

    float *e, *h, *kse, *beta, *c, *bse;
    uint32_t *etf, *x1tf, *htf, *wt1, *wt2, *wtse;
    cudaGetSymbolAddress((void**)&e,    g_e);
    cudaGetSymbolAddress((void**)&etf,  g_etf);
    cudaGetSymbolAddress((void**)&x1tf, g_x1tf);
    cudaGetSymbolAddress((void**)&h,    g_h);
    cudaGetSymbolAddress((void**)&htf,  g_htf);
    cudaGetSymbolAddress((void**)&kse,  g_kse);
    cudaGetSymbolAddress((void**)&beta, g_beta);
    cudaGetSymbolAddress((void**)&c,    g_c);
    cudaGetSymbolAddress((void**)&wt1,  g_wt1);
    cudaGetSymbolAddress((void**)&wt2,  g_wt2);
    cudaGetSymbolAddress((void**)&wtse, g_wtse);
    cudaGetSymbolAddress((void**)&bse,  g_bse);

    // weight prep (tf32 bits, transposed to [N][K])
    transpose_tf32_kernel<<<dim3(1024 / 32, 512 / 32), 256>>>(ff_w1, wt1, 512, 1024);
    transpose_tf32_kernel<<<dim3(512 / 32, 1024 / 32), 256>>>(ff_w2, wt2, 1024, 512);
    transpose_tf32_kernel<<<dim3(256 / 32, 512 / 32),  256>>>(sem_w, wtse, 512, 256);
    transpose_tf32_kernel<<<dim3(256 / 32, 512 / 32),  256>>>(epi_w, wtse + 256 * 512, 512, 256);
    pack_bias_kernel<<<2, 256>>>(sem_b, epi_b, bse);

    gather_kernel<<<BL * (Hdim / 4) / 256, 256>>>(seq, embed, e, etf);

    // FFN GEMM1: relu -> tf32 out
    tc_gemm_kernel<0><<<dim3(2 * Hdim / 128, BL / 128), 256>>>(
        etf, wt1, ff_b1, nullptr, x1tf, BL, 2 * Hdim, Hdim);

    // FFN GEMM2: + residual e -> fp32 h
    tc_gemm_kernel<1><<<dim3(Hdim / 128, BL / 128), 256>>>(
        x1tf, wt2, ff_b2, e, h, BL, Hdim, 2 * Hdim);

    ln_kernel<<<BL / 8, 256>>>(h, htf, ln_g, ln_b);

    // fused sem|epi projection -> kse[BL][512] fp32
    tc_gemm_kernel<2><<<dim3(512 / 128, BL / 128), 256>>>(
        htf, wtse, bse, nullptr, kse, BL, 512, Hdim);

    beta_kernel<<<2 * BL / 8, 256>>>(kse, beta);

    scan_kernel<<<Bsz * 2 * 2, 512>>>(kse, beta, c);

    out_gemm_kernel<<<Vvoc / 256, 256>>>(c, out_w, out_b, out);
}